// round 13
// baseline (speedup 1.0000x reference)
#include <cuda_runtime.h>
#include <cstdint>
#include <cstddef>

#define N_ROWS 131072
#define DIM    512
#define NCLU   512

static constexpr float SX     = 6.0f / 127.0f;   // fixed x quant scale
static constexpr float INV_SX = 127.0f / 6.0f;

// ---------------------------------------------------------------------------
// Device-global scratch (centers, quantized)
// ---------------------------------------------------------------------------
__device__ int8_t g_cq[(size_t)NCLU * DIM];
__device__ float  g_c2[NCLU];   // exact ||c||^2
__device__ float  g_cs[NCLU];   // per-row scale max|c|/127

// ---------------------------------------------------------------------------
// Helpers
// ---------------------------------------------------------------------------
__device__ __forceinline__ uint32_t smem_to_u32(const void* smem_ptr) {
    uint32_t addr;
    asm("{ .reg .u64 tmp; cvta.to.shared.u64 tmp, %1; cvt.u32.u64 %0, tmp; }"
        : "=r"(addr) : "l"(smem_ptr));
    return addr;
}
__device__ __forceinline__ void cp16(uint32_t dst_smem, const void* src) {
    asm volatile("cp.async.cg.shared.global [%0], [%1], 16;"
                 :: "r"(dst_smem), "l"(src));
}
__device__ __forceinline__ void cp_commit() {
    asm volatile("cp.async.commit_group;");
}
template <int N>
__device__ __forceinline__ void cp_wait() {
    asm volatile("cp.async.wait_group %0;" :: "n"(N));
}
__device__ __forceinline__ float frcp(float a) {
    float r;
    asm("rcp.approx.f32 %0, %1;" : "=f"(r) : "f"(a));
    return r;
}
__device__ __forceinline__ void ldsm4(uint32_t* r, uint32_t addr) {
    asm volatile("ldmatrix.sync.aligned.m8n8.x4.shared.b16 {%0,%1,%2,%3}, [%4];"
                 : "=r"(r[0]), "=r"(r[1]), "=r"(r[2]), "=r"(r[3]) : "r"(addr));
}
__device__ __forceinline__ float4 lds_f4(uint32_t addr) {
    float4 v;
    asm volatile("ld.shared.v4.f32 {%0,%1,%2,%3}, [%4];"
                 : "=f"(v.x), "=f"(v.y), "=f"(v.z), "=f"(v.w) : "r"(addr));
    return v;
}
__device__ __forceinline__ void sts_v4(uint32_t addr, uint32_t a, uint32_t b,
                                       uint32_t c, uint32_t d) {
    asm volatile("st.shared.v4.b32 [%0], {%1,%2,%3,%4};"
                 :: "r"(addr), "r"(a), "r"(b), "r"(c), "r"(d) : "memory");
}
// s8 x s8 -> s32, K=32 per instruction (base ISA since sm_80)
__device__ __forceinline__ void mma16832i(int* c, const uint32_t* a, const uint32_t* b) {
    asm volatile(
        "mma.sync.aligned.m16n8k32.row.col.s32.s8.s8.s32 "
        "{%0,%1,%2,%3}, {%4,%5,%6,%7}, {%8,%9}, {%0,%1,%2,%3};"
        : "+r"(c[0]), "+r"(c[1]), "+r"(c[2]), "+r"(c[3])
        : "r"(a[0]), "r"(a[1]), "r"(a[2]), "r"(a[3]), "r"(b[0]), "r"(b[1]));
}
// pack 4 s32 -> 4 saturated s8 bytes (little-endian e0..e3)
__device__ __forceinline__ uint32_t pack_s8(int e0, int e1, int e2, int e3) {
    uint32_t r, z = 0;
    asm("cvt.pack.sat.s8.s32.b32 %0, %1, %2, %3;" : "=r"(r) : "r"(e3), "r"(e2), "r"(z));
    asm("cvt.pack.sat.s8.s32.b32 %0, %1, %2, %3;" : "=r"(r) : "r"(e1), "r"(e0), "r"(r));
    return r;
}
__device__ __forceinline__ uint32_t quant4(float a, float b, float c, float d) {
    return pack_s8(__float2int_rn(a * INV_SX), __float2int_rn(b * INV_SX),
                   __float2int_rn(c * INV_SX), __float2int_rn(d * INV_SX));
}

// ---------------------------------------------------------------------------
// Prep centers: fp32 -> int8 (per-row scale) + exact row norms. One row/warp.
// ---------------------------------------------------------------------------
__global__ void prep_c_kernel(const float* __restrict__ c) {
    int row = blockIdx.x * 8 + (threadIdx.x >> 5);
    if (row >= NCLU) return;
    int lane = threadIdx.x & 31;
    const float4* sr = (const float4*)(c + (size_t)row * DIM);
    float4 v[4];
    float s = 0.f, m = 0.f;
    #pragma unroll
    for (int j = 0; j < 4; j++) {
        v[j] = sr[lane * 4 + j];           // cols lane*16 + j*4 .. +3
        s += v[j].x * v[j].x + v[j].y * v[j].y + v[j].z * v[j].z + v[j].w * v[j].w;
        m = fmaxf(m, fmaxf(fmaxf(fabsf(v[j].x), fabsf(v[j].y)),
                           fmaxf(fabsf(v[j].z), fabsf(v[j].w))));
    }
    #pragma unroll
    for (int o = 16; o; o >>= 1) {
        s += __shfl_xor_sync(0xffffffffu, s, o);
        m = fmaxf(m, __shfl_xor_sync(0xffffffffu, m, o));
    }
    float inv = (m > 0.f) ? 127.0f / m : 0.f;
    uint4 p;
    p.x = pack_s8(__float2int_rn(v[0].x * inv), __float2int_rn(v[0].y * inv),
                  __float2int_rn(v[0].z * inv), __float2int_rn(v[0].w * inv));
    p.y = pack_s8(__float2int_rn(v[1].x * inv), __float2int_rn(v[1].y * inv),
                  __float2int_rn(v[1].z * inv), __float2int_rn(v[1].w * inv));
    p.z = pack_s8(__float2int_rn(v[2].x * inv), __float2int_rn(v[2].y * inv),
                  __float2int_rn(v[2].z * inv), __float2int_rn(v[2].w * inv));
    p.w = pack_s8(__float2int_rn(v[3].x * inv), __float2int_rn(v[3].y * inv),
                  __float2int_rn(v[3].z * inv), __float2int_rn(v[3].w * inv));
    ((uint4*)(g_cq + (size_t)row * DIM))[lane] = p;
    if (lane == 0) { g_c2[row] = s; g_cs[row] = m / 127.0f; }
}

// ---------------------------------------------------------------------------
// Fused int8 GEMM + t-student epilogue.
// 512 threads / 16 warps (2m x 8n), warp tile 64x32, CTA tile 128x256.
// Cluster of 2 CTAs covers the 512 clusters (DSMEM row-sum exchange).
// K processed in 4 super-chunks of 128 bytes (4 x k32 mma each).
// A: cp.async fp32 staging (self-owned) -> quantize s8 -> Ahq (dbl-buffered).
// ||x||^2 exact fp32 during quantization.
// ---------------------------------------------------------------------------
static constexpr int TM = 128, TN = 256, KSUP = 128, NSUP = DIM / KSUP;  // 4
static constexpr int AF_BYTES  = TM * 64 * 4;               // 32768 / unit (2 units)
static constexpr int AHQ_BYTES = TM * KSUP;                  // 16384 / buf
static constexpr int B_BYTES   = TN * KSUP;                  // 32768 / stage
static constexpr int AF_OFF   = 0;                            // 2 units = 65536
static constexpr int AHQ_OFF  = 2 * AF_BYTES;                 // 65536, 2 bufs
static constexpr int B_OFF    = AHQ_OFF + 2 * AHQ_BYTES;      // 98304, 2 stages
static constexpr int C2_OFF   = B_OFF + 2 * B_BYTES;          // 163840 (256 f32)
static constexpr int FS_OFF   = C2_OFF + TN * 4;              // 164864 (256 f32)
static constexpr int X2_OFF   = FS_OFF + TN * 4;              // 165888 (128 f32)
static constexpr int RED_OFF  = X2_OFF + TM * 4;              // 166400 (128x8)
static constexpr int PEER_OFF = RED_OFF + TM * 8 * 4;         // 170496
static constexpr int INV_OFF  = PEER_OFF + TM * 4;            // 171008
static constexpr int SMEM_TOTAL = INV_OFF + TM * 4;           // 171520

__global__ void __launch_bounds__(512, 1) __cluster_dims__(2, 1, 1)
gemm_kernel(const float* __restrict__ x, float* __restrict__ out) {
    extern __shared__ __align__(1024) char smem[];
    uint32_t sb = smem_to_u32(smem);
    int tid = threadIdx.x;
    int wid = tid >> 5, lane = tid & 31;
    int mtile = blockIdx.x >> 1;
    int nhalf = blockIdx.x & 1;
    int wg = wid & 1;            // m stripe (2 x 64 rows)
    int wn = wid >> 1;           // n group (8 x 32 cols)

    float* c2s  = (float*)(smem + C2_OFF);
    float* fss  = (float*)(smem + FS_OFF);
    float* x2s  = (float*)(smem + X2_OFF);
    float* red  = (float*)(smem + RED_OFF);
    float* peer = (float*)(smem + PEER_OFF);
    float* invs = (float*)(smem + INV_OFF);

    for (int i = tid; i < TN; i += 512) {
        c2s[i] = g_c2[nhalf * TN + i];
        fss[i] = 2.0f * SX * g_cs[nhalf * TN + i];
    }

    const float* asrc0 = x + (size_t)mtile * TM * DIM;

    // A ownership: row ar = tid>>2 (4 threads/row), quarter cq = tid&3.
    int ar = tid >> 2, cq = tid & 3;
    int cqx = cq ^ (ar & 3);                 // banked AF slot
    uint32_t AF_slot0 = sb + AF_OFF + (uint32_t)ar * 256 + (uint32_t)cqx * 64;
    uint32_t aswz = (uint32_t)(ar & 7) << 4;

    auto load_A = [&](int t) {               // both 64-col units of super t
        #pragma unroll
        for (int u = 0; u < 2; u++) {
            const float* ap = asrc0 + (size_t)ar * DIM + t * KSUP + u * 64 + cq * 16;
            uint32_t d = AF_slot0 + u * AF_BYTES;
            #pragma unroll
            for (int i = 0; i < 4; i++) cp16(d + i * 16, ap + i * 4);
        }
        cp_commit();
    };
    auto load_B = [&](int t) {
        uint32_t Bb = sb + B_OFF + (t & 1) * B_BYTES;
        const int8_t* bp = g_cq + (size_t)(nhalf * TN) * DIM + t * KSUP;
        #pragma unroll
        for (int i = 0; i < 4; i++) {        // 1024 chunks of 16B
            int idx = tid + i * 512;
            int br = idx >> 3, c = idx & 7;
            cp16(Bb + (uint32_t)br * 128 + (((uint32_t)c * 16) ^ ((uint32_t)(br & 7) << 4)),
                 bp + (size_t)br * DIM + c * 16);
        }
        cp_commit();
    };

    float xacc = 0.f;                        // exact ||x||^2 partial (row ar)

    auto convert = [&](int t) {              // AF (own slots) -> Ahq[t&1]
        uint32_t Ab = sb + AHQ_OFF + (t & 1) * AHQ_BYTES + (uint32_t)ar * 128;
        #pragma unroll
        for (int u = 0; u < 2; u++) {
            uint32_t s = AF_slot0 + u * AF_BYTES;
            float4 v0 = lds_f4(s);
            float4 v1 = lds_f4(s + 16);
            float4 v2 = lds_f4(s + 32);
            float4 v3 = lds_f4(s + 48);
            xacc += v0.x * v0.x + v0.y * v0.y + v0.z * v0.z + v0.w * v0.w
                  + v1.x * v1.x + v1.y * v1.y + v1.z * v1.z + v1.w * v1.w
                  + v2.x * v2.x + v2.y * v2.y + v2.z * v2.z + v2.w * v2.w
                  + v3.x * v3.x + v3.y * v3.y + v3.z * v3.z + v3.w * v3.w;
            uint32_t chunk = (uint32_t)(u * 4 + cq);
            sts_v4(Ab + ((chunk * 16) ^ aswz),
                   quant4(v0.x, v0.y, v0.z, v0.w), quant4(v1.x, v1.y, v1.z, v1.w),
                   quant4(v2.x, v2.y, v2.z, v2.w), quant4(v3.x, v3.y, v3.z, v3.w));
        }
    };

    // ldmatrix lane addressing (128B rows, SW128)
    int ri = lane & 7;
    uint32_t mask = (uint32_t)ri << 4;
    uint32_t a_row0 = (uint32_t)(wg * 64 + ((lane >> 3) & 1) * 8 + ri) * 128;
    uint32_t akoff  = (uint32_t)(lane >> 4) * 16;
    uint32_t b_row0 = (uint32_t)(wn * 32 + (lane >> 4) * 8 + ri) * 128;
    uint32_t bkoff  = (uint32_t)((lane >> 3) & 1) * 16;

    int acc[4][4][4] = {};                   // warp tile 64x32, s32

    // ---- Prologue (serial, 4 supers only) ----
    load_A(0);
    cp_wait<0>();
    convert(0);                              // -> Ahq[0]
    load_A(1);
    load_B(0);
    cp_wait<0>();
    __syncthreads();                         // Ahq[0] + B[0] visible
    load_B(1);

    for (int t = 0; t < NSUP; t++) {
        uint32_t Ab = sb + AHQ_OFF + (t & 1) * AHQ_BYTES;
        uint32_t Bb = sb + B_OFF + (t & 1) * B_BYTES;

        #pragma unroll
        for (int ks = 0; ks < 4; ks++) {
            if (ks == 1 && t < NSUP - 1) {
                cp_wait<1>();                // A(t+1) done (B(t+1) may pend)
                convert(t + 1);              // -> Ahq[(t+1)&1]
                if (t + 2 < NSUP) load_A(t + 2);
            }
            uint32_t a[4][4], b[2][4];
            uint32_t akb = ((uint32_t)ks * 32 + akoff) ^ mask;
            uint32_t bkb = ((uint32_t)ks * 32 + bkoff) ^ mask;
            #pragma unroll
            for (int mt = 0; mt < 4; mt++)
                ldsm4(a[mt], Ab + a_row0 + (uint32_t)(mt * 2048) + akb);
            #pragma unroll
            for (int gg = 0; gg < 2; gg++)
                ldsm4(b[gg], Bb + b_row0 + (uint32_t)(gg * 2048) + bkb);
            #pragma unroll
            for (int mt = 0; mt < 4; mt++)
                #pragma unroll
                for (int nt = 0; nt < 4; nt++)
                    mma16832i(acc[mt][nt], a[mt], b[nt >> 1] + (nt & 1) * 2);
        }

        if (t < NSUP - 1) {
            if (t + 2 < NSUP) cp_wait<1>();  // B(t+1) done; A(t+2) may pend
            else cp_wait<0>();               // B(t+1) done
        }
        __syncthreads();                     // publish Ahq[(t+1)&1] + B reuse safe
        if (t + 2 < NSUP) load_B(t + 2);
    }

    // ---------------- Epilogue ----------------
    // exact ||x||^2: 4 threads per row -> quad reduce
    xacc += __shfl_xor_sync(0xffffffffu, xacc, 1);
    xacc += __shfl_xor_sync(0xffffffffu, xacc, 2);
    if ((lane & 3) == 0) x2s[ar] = xacc;
    __syncthreads();

    int g = lane >> 2, qa = lane & 3;

    // Pass 1: row-sums of q
    float rs[4][2];
    #pragma unroll
    for (int mt = 0; mt < 4; mt++) {
        #pragma unroll
        for (int h = 0; h < 2; h++) {
            int row = wg * 64 + mt * 16 + h * 8 + g;
            float x2v = x2s[row];
            float p = 0.f;
            #pragma unroll
            for (int nt = 0; nt < 4; nt++) {
                int col = wn * 32 + nt * 8 + qa * 2;
                float d0 = (float)acc[mt][nt][h * 2 + 0];
                float d1 = (float)acc[mt][nt][h * 2 + 1];
                p += frcp(1.f + fmaxf(fmaf(-fss[col], d0, x2v + c2s[col]), 0.f));
                p += frcp(1.f + fmaxf(fmaf(-fss[col + 1], d1, x2v + c2s[col + 1]), 0.f));
            }
            rs[mt][h] = p;
        }
    }
    #pragma unroll
    for (int mt = 0; mt < 4; mt++)
        #pragma unroll
        for (int h = 0; h < 2; h++) {
            rs[mt][h] += __shfl_xor_sync(0xffffffffu, rs[mt][h], 1);
            rs[mt][h] += __shfl_xor_sync(0xffffffffu, rs[mt][h], 2);
        }
    if (qa == 0) {
        #pragma unroll
        for (int mt = 0; mt < 4; mt++)
            #pragma unroll
            for (int h = 0; h < 2; h++)
                red[(wg * 64 + mt * 16 + h * 8 + g) * 8 + wn] = rs[mt][h];
    }
    __syncthreads();

    float L = 0.f;
    if (tid < TM) {
        #pragma unroll
        for (int j = 0; j < 8; j++) L += red[tid * 8 + j];
        uint32_t paddr;
        asm volatile("mapa.shared::cluster.u32 %0, %1, %2;"
                     : "=r"(paddr) : "r"(sb + PEER_OFF + tid * 4), "r"(nhalf ^ 1));
        asm volatile("st.shared::cluster.f32 [%0], %1;" :: "r"(paddr), "f"(L) : "memory");
    }
    asm volatile("barrier.cluster.arrive.aligned;" ::: "memory");
    asm volatile("barrier.cluster.wait.aligned;" ::: "memory");
    if (tid < TM) invs[tid] = frcp(L + peer[tid]);
    __syncthreads();

    // Pass 2: recompute q, normalize, store
    float* outbase = out + (size_t)mtile * TM * NCLU + nhalf * TN;
    #pragma unroll
    for (int mt = 0; mt < 4; mt++) {
        #pragma unroll
        for (int h = 0; h < 2; h++) {
            int row = wg * 64 + mt * 16 + h * 8 + g;
            float x2v = x2s[row];
            float inv = invs[row];
            float* orow = outbase + (size_t)row * NCLU + wn * 32;
            #pragma unroll
            for (int nt = 0; nt < 4; nt++) {
                int col = wn * 32 + nt * 8 + qa * 2;
                float d0 = (float)acc[mt][nt][h * 2 + 0];
                float d1 = (float)acc[mt][nt][h * 2 + 1];
                float2 v;
                v.x = frcp(1.f + fmaxf(fmaf(-fss[col], d0, x2v + c2s[col]), 0.f)) * inv;
                v.y = frcp(1.f + fmaxf(fmaf(-fss[col + 1], d1, x2v + c2s[col + 1]), 0.f)) * inv;
                *(float2*)(orow + nt * 8 + qa * 2) = v;
            }
        }
    }
}

// ---------------------------------------------------------------------------
// Launch
// ---------------------------------------------------------------------------
extern "C" void kernel_launch(void* const* d_in, const int* in_sizes, int n_in,
                              void* d_out, int out_size) {
    const float* x  = (const float*)d_in[0];
    const float* cc = (const float*)d_in[1];
    float* out = (float*)d_out;

    cudaFuncSetAttribute(gemm_kernel,
                         cudaFuncAttributeMaxDynamicSharedMemorySize, SMEM_TOTAL);

    prep_c_kernel<<<NCLU / 8, 256>>>(cc);
    gemm_kernel<<<(N_ROWS / TM) * 2, 512, SMEM_TOTAL>>>(x, out);
}

// round 14
// speedup vs baseline: 2.6773x; 2.6773x over previous
#include <cuda_runtime.h>
#include <cuda_fp16.h>
#include <cstdint>
#include <cstddef>

#define N_ROWS 131072
#define DIM    512
#define NCLU   512

// ---------------------------------------------------------------------------
// Device-global scratch (centers only)
// ---------------------------------------------------------------------------
__device__ __half g_ch[(size_t)NCLU * DIM];
__device__ float g_c2[NCLU];

// ---------------------------------------------------------------------------
// Helpers
// ---------------------------------------------------------------------------
__device__ __forceinline__ uint32_t smem_to_u32(const void* smem_ptr) {
    uint32_t addr;
    asm("{ .reg .u64 tmp; cvta.to.shared.u64 tmp, %1; cvt.u32.u64 %0, tmp; }"
        : "=r"(addr) : "l"(smem_ptr));
    return addr;
}
__device__ __forceinline__ void cp16(uint32_t dst_smem, const void* src) {
    asm volatile("cp.async.cg.shared.global [%0], [%1], 16;"
                 :: "r"(dst_smem), "l"(src));
}
__device__ __forceinline__ void cp_commit() {
    asm volatile("cp.async.commit_group;");
}
template <int N>
__device__ __forceinline__ void cp_wait() {
    asm volatile("cp.async.wait_group %0;" :: "n"(N));
}
__device__ __forceinline__ float frcp(float a) {
    float r;
    asm("rcp.approx.f32 %0, %1;" : "=f"(r) : "f"(a));
    return r;
}
__device__ __forceinline__ void ldsm4(uint32_t* r, uint32_t addr) {
    asm volatile("ldmatrix.sync.aligned.m8n8.x4.shared.b16 {%0,%1,%2,%3}, [%4];"
                 : "=r"(r[0]), "=r"(r[1]), "=r"(r[2]), "=r"(r[3]) : "r"(addr));
}
__device__ __forceinline__ float4 lds_f4(uint32_t addr) {
    float4 v;
    asm volatile("ld.shared.v4.f32 {%0,%1,%2,%3}, [%4];"
                 : "=f"(v.x), "=f"(v.y), "=f"(v.z), "=f"(v.w) : "r"(addr));
    return v;
}
__device__ __forceinline__ void sts_v2(uint32_t addr, uint32_t a, uint32_t b) {
    asm volatile("st.shared.v2.b32 [%0], {%1,%2};"
                 :: "r"(addr), "r"(a), "r"(b) : "memory");
}
__device__ __forceinline__ void mma16816h(uint32_t* c, const uint32_t* a, const uint32_t* b) {
    asm volatile(
        "mma.sync.aligned.m16n8k16.row.col.f16.f16.f16.f16 "
        "{%0,%1}, {%2,%3,%4,%5}, {%6,%7}, {%0,%1};"
        : "+r"(c[0]), "+r"(c[1])
        : "r"(a[0]), "r"(a[1]), "r"(a[2]), "r"(a[3]), "r"(b[0]), "r"(b[1]));
}
__device__ __forceinline__ uint32_t pack_f16(float a, float b) {
    union { __half2 h; uint32_t u; } pk;
    pk.h = __floats2half2_rn(a, b);
    return pk.u;
}
__device__ __forceinline__ void barg(int id) {
    asm volatile("bar.sync %0, 256;" :: "r"(id) : "memory");
}
__device__ __forceinline__ void barp(int id) {
    asm volatile("bar.sync %0, 64;" :: "r"(id) : "memory");
}

// ---------------------------------------------------------------------------
// Prep centers: fp32 -> fp16 + row norms (one row per warp). ~2us.
// ---------------------------------------------------------------------------
__global__ void prep_c_kernel(const float* __restrict__ c) {
    int row = blockIdx.x * 8 + (threadIdx.x >> 5);
    if (row >= NCLU) return;
    int lane = threadIdx.x & 31;
    const float4* sr = (const float4*)(c + (size_t)row * DIM);
    uint2* dr = (uint2*)(g_ch + (size_t)row * DIM);
    float s = 0.f;
    #pragma unroll
    for (int t = 0; t < 4; t++) {
        float4 v = sr[lane + 32 * t];
        s += v.x * v.x + v.y * v.y + v.z * v.z + v.w * v.w;
        uint2 u;
        u.x = pack_f16(v.x, v.y);
        u.y = pack_f16(v.z, v.w);
        dr[lane + 32 * t] = u;
    }
    #pragma unroll
    for (int o = 16; o; o >>= 1) s += __shfl_xor_sync(0xffffffffu, s, o);
    if (lane == 0) g_c2[row] = s;
}

// ---------------------------------------------------------------------------
// PERSISTENT fused GEMM + t-student epilogue (R12 structure made persistent).
// grid = #SMs; each CTA loops mtiles with stride gridDim.x. The K-chunk
// pipeline continues ACROSS tile boundaries: chunk prefetch/convert at
// kc=6,7 wraps into the next tile's chunks 0,1, so the epilogue of tile t
// overlaps the prologue loads of tile t+stride.
// 512 threads / 16 warps, CTA tile 128x512, warp tile 64x64, fp16 HMMA.
// Scoped named barriers only in the mainloop (no CTA-wide sync).
// ---------------------------------------------------------------------------
static constexpr int TM = 128, KC = 64, NUM_KC = DIM / KC;  // 8
static constexpr int NTILES = N_ROWS / TM;                  // 1024
static constexpr int AF_BYTES  = TM * KC * 4;               // 32768 (1 buf)
static constexpr int AHF_BYTES = TM * KC * 2;               // 16384 / buf
static constexpr int B_BYTES   = NCLU * KC * 2;             // 65536 / stage
static constexpr int AF_OFF   = 0;
static constexpr int AHF_OFF  = AF_BYTES;                    // 32768, 2 bufs
static constexpr int B_OFF    = AHF_OFF + 2 * AHF_BYTES;     // 65536, 2 stages
static constexpr int C2_OFF   = B_OFF + 2 * B_BYTES;         // 196608
static constexpr int X2_OFF   = C2_OFF + NCLU * 4;           // 198656
static constexpr int RED_OFF  = X2_OFF + TM * 4;             // 199168 (128x8)
static constexpr int INV_OFF  = RED_OFF + TM * 8 * 4;        // 203264
static constexpr int SMEM_TOTAL = INV_OFF + TM * 4;          // 203776

__global__ void __launch_bounds__(512, 1)
gemm_kernel(const float* __restrict__ x, float* __restrict__ out) {
    extern __shared__ __align__(1024) char smem[];
    uint32_t sb = smem_to_u32(smem);
    int tid = threadIdx.x;
    int wid = tid >> 5, lane = tid & 31;
    // SMSP-balanced mapping: each SMSP hosts 2 warps of each A-group.
    int wg = (wid >> 2) & 1;                       // A-stripe group (0/1)
    int wn = (wid & 3) | ((wid >> 3) << 2);        // B column group (0..7)

    float* c2s  = (float*)(smem + C2_OFF);
    float* x2s  = (float*)(smem + X2_OFF);
    float* red  = (float*)(smem + RED_OFF);
    float* invs = (float*)(smem + INV_OFF);

    for (int i = tid; i < NCLU; i += 512) c2s[i] = g_c2[i];
    __syncthreads();

    // ---- A ownership: row ar (fixed per thread), 4 fp32-chunks per kc ----
    int ar = wg * 64 + wn * 8 + (lane >> 2);
    int ac0 = lane & 3;
    uint32_t aswz = (uint32_t)(ar & 7) << 4;

    auto load_GA = [&](const float* asrc0, int kc) {
        const float* ap = asrc0 + (size_t)ar * DIM + kc * KC;
        uint32_t AfR = sb + AF_OFF + (uint32_t)ar * 256;
        #pragma unroll
        for (int i = 0; i < 4; i++) {
            int c = ac0 + 4 * i;
            cp16(AfR + (((uint32_t)c * 16) ^ aswz), ap + c * 4);
        }
        cp_commit();
    };
    auto load_GB = [&](int kc) {   // B is tile-invariant (centers)
        uint32_t Bb = sb + B_OFF + (kc & 1) * B_BYTES;
        const __half* bp = g_ch + kc * KC;
        #pragma unroll
        for (int i = 0; i < 8; i++) {
            int br = wn * 64 + wg * 32 + (lane >> 3) + 4 * i;
            int c = lane & 7;
            cp16(Bb + (uint32_t)br * 128 + (((uint32_t)c * 16) ^ ((uint32_t)(br & 7) << 4)),
                 bp + (size_t)br * DIM + c * 8);
        }
        cp_commit();
    };
    auto convert = [&](int buf, float& xa) {   // AF (own slots) -> Ahf[buf]
        uint32_t AfR = sb + AF_OFF + (uint32_t)ar * 256;
        uint32_t AbR = sb + AHF_OFF + buf * AHF_BYTES + (uint32_t)ar * 128;
        #pragma unroll
        for (int i = 0; i < 4; i++) {
            int c = ac0 + 4 * i;
            float4 v = lds_f4(AfR + (((uint32_t)c * 16) ^ aswz));
            xa += v.x * v.x + v.y * v.y + v.z * v.z + v.w * v.w;
            sts_v2(AbR + ((((uint32_t)(c >> 1)) * 16) ^ aswz) + (c & 1) * 8,
                   pack_f16(v.x, v.y), pack_f16(v.z, v.w));
        }
    };

    // ldmatrix lane addressing
    int ri = lane & 7;
    uint32_t mask = (uint32_t)ri << 4;
    uint32_t a_row0 = (uint32_t)(wg * 64 + ((lane >> 3) & 1) * 8 + ri) * 128;
    uint32_t akoff  = (uint32_t)(lane >> 4) * 16;
    uint32_t b_row0 = (uint32_t)(wn * 64 + (lane >> 4) * 8 + ri) * 128;
    uint32_t bkoff  = (uint32_t)((lane >> 3) & 1) * 16;

    int idg = 1 + wg;     // named barrier ids: A groups 1,2
    int idp = 3 + wn;     // B pairs 3..10

    int mtile = blockIdx.x;
    const float* asrc_cur = x + (size_t)mtile * TM * DIM;
    float xcur = 0.f, xnext = 0.f;

    // ---- Prologue (first tile only) ----
    load_GA(asrc_cur, 0); load_GB(0);
    load_GB(1);
    cp_wait<1>();                 // GA0 + GB0 done (own)
    convert(0, xcur);             // AF(A0) -> Ahf[0]; AF slots free
    load_GA(asrc_cur, 1);
    barg(idg); barp(idp);         // publish Ahf[0] + B[0]

    while (true) {
        bool last_tile = (mtile + (int)gridDim.x >= NTILES);
        const float* asrc_next = asrc_cur + (size_t)gridDim.x * TM * DIM;

        uint32_t acc[4][8][2] = {};   // fresh accumulators per tile

        for (int kc = 0; kc < NUM_KC; kc++) {
            int s = kc & 1;
            uint32_t Ab = sb + AHF_OFF + s * AHF_BYTES;
            uint32_t Bb = sb + B_OFF + s * B_BYTES;
            bool next1 = !(last_tile && kc == NUM_KC - 1);  // chunk kc+1 exists

            #pragma unroll
            for (int ks = 0; ks < 4; ks++) {
                if (ks == 1 && next1) {
                    cp_wait<0>();                  // GA,GB of chunk kc+1 done (own)
                    if (kc == NUM_KC - 1) convert(0, xnext);   // next tile chunk 0
                    else convert((kc + 1) & 1, xcur);
                    int nk = kc + 2;               // prefetch chunk kc+2 (A)
                    if (nk < NUM_KC) load_GA(asrc_cur, nk);
                    else if (!last_tile) load_GA(asrc_next, nk - NUM_KC);
                }
                uint32_t a[4][4], b[4][4];
                uint32_t akb = (akoff + ks * 32) ^ mask;
                uint32_t bkb = (bkoff + ks * 32) ^ mask;
                #pragma unroll
                for (int mt = 0; mt < 4; mt++)
                    ldsm4(a[mt], Ab + a_row0 + (uint32_t)(mt * 2048) + akb);
                #pragma unroll
                for (int gg = 0; gg < 4; gg++)
                    ldsm4(b[gg], Bb + b_row0 + (uint32_t)(gg * 2048) + bkb);
                #pragma unroll
                for (int mt = 0; mt < 4; mt++)
                    #pragma unroll
                    for (int nt = 0; nt < 8; nt++)
                        mma16816h(acc[mt][nt], a[mt], b[nt >> 1] + (nt & 1) * 2);
            }

            barg(idg);            // group done with Ahf[s]; Ahf[s^1] published
            barp(idp);            // pair done with B[s]
            {
                int nk = kc + 2;  // refill freed B stage with chunk kc+2
                if (nk < NUM_KC) load_GB(nk);
                else if (!last_tile) load_GB(nk - NUM_KC);
            }
        }

        // ---------------- Epilogue for tile mtile ----------------
        __syncthreads();          // all warps past previous x2s/invs reads
        {
            float xr = xcur;
            xr += __shfl_xor_sync(0xffffffffu, xr, 1);
            xr += __shfl_xor_sync(0xffffffffu, xr, 2);
            if ((lane & 3) == 0) x2s[ar] = xr;
        }
        __syncthreads();

        int g = lane >> 2, qa = lane & 3;

        // Pass 1: row-sums of q
        float rs[4][2];
        #pragma unroll
        for (int mt = 0; mt < 4; mt++) {
            #pragma unroll
            for (int h = 0; h < 2; h++) {
                int row = wg * 64 + mt * 16 + h * 8 + g;
                float x2v = x2s[row];
                float p = 0.f;
                #pragma unroll
                for (int nt = 0; nt < 8; nt++) {
                    int col = wn * 64 + nt * 8 + qa * 2;
                    union { uint32_t u; __half2 h2; } cvt;
                    cvt.u = acc[mt][nt][h];
                    float2 d = __half22float2(cvt.h2);
                    p += frcp(1.f + fmaxf(fmaf(-2.f, d.x, x2v + c2s[col]), 0.f));
                    p += frcp(1.f + fmaxf(fmaf(-2.f, d.y, x2v + c2s[col + 1]), 0.f));
                }
                rs[mt][h] = p;
            }
        }
        #pragma unroll
        for (int mt = 0; mt < 4; mt++)
            #pragma unroll
            for (int h = 0; h < 2; h++) {
                rs[mt][h] += __shfl_xor_sync(0xffffffffu, rs[mt][h], 1);
                rs[mt][h] += __shfl_xor_sync(0xffffffffu, rs[mt][h], 2);
            }
        if (qa == 0) {
            #pragma unroll
            for (int mt = 0; mt < 4; mt++)
                #pragma unroll
                for (int h = 0; h < 2; h++)
                    red[(wg * 64 + mt * 16 + h * 8 + g) * 8 + wn] = rs[mt][h];
        }
        __syncthreads();
        if (tid < TM) {
            float L = 0.f;
            #pragma unroll
            for (int j = 0; j < 8; j++) L += red[tid * 8 + j];
            invs[tid] = frcp(L);
        }
        __syncthreads();

        // Pass 2: recompute q, normalize, store
        float* outbase = out + (size_t)mtile * TM * NCLU;
        #pragma unroll
        for (int mt = 0; mt < 4; mt++) {
            #pragma unroll
            for (int h = 0; h < 2; h++) {
                int row = wg * 64 + mt * 16 + h * 8 + g;
                float x2v = x2s[row];
                float inv = invs[row];
                float* orow = outbase + (size_t)row * NCLU + wn * 64;
                #pragma unroll
                for (int nt = 0; nt < 8; nt++) {
                    int col = wn * 64 + nt * 8 + qa * 2;
                    union { uint32_t u; __half2 h2; } cvt;
                    cvt.u = acc[mt][nt][h];
                    float2 d = __half22float2(cvt.h2);
                    float2 v;
                    v.x = frcp(1.f + fmaxf(fmaf(-2.f, d.x, x2v + c2s[col]), 0.f)) * inv;
                    v.y = frcp(1.f + fmaxf(fmaf(-2.f, d.y, x2v + c2s[col + 1]), 0.f)) * inv;
                    *(float2*)(orow + nt * 8 + qa * 2) = v;
                }
            }
        }

        if (last_tile) break;
        mtile += (int)gridDim.x;
        asrc_cur = asrc_next;
        xcur = xnext;
        xnext = 0.f;
        // Ahf[0]/B[0] for the new tile were converted/loaded during kc=6,7
        // and published by the final barg/barp — the mainloop continues
        // without a prologue.
    }
}

// ---------------------------------------------------------------------------
// Launch
// ---------------------------------------------------------------------------
extern "C" void kernel_launch(void* const* d_in, const int* in_sizes, int n_in,
                              void* d_out, int out_size) {
    const float* x  = (const float*)d_in[0];
    const float* cc = (const float*)d_in[1];
    float* out = (float*)d_out;

    cudaFuncSetAttribute(gemm_kernel,
                         cudaFuncAttributeMaxDynamicSharedMemorySize, SMEM_TOTAL);

    int dev = 0, nsm = 148;
    cudaGetDevice(&dev);
    cudaDeviceGetAttribute(&nsm, cudaDevAttrMultiProcessorCount, dev);

    prep_c_kernel<<<NCLU / 8, 256>>>(cc);
    gemm_kernel<<<nsm, 512, SMEM_TOTAL>>>(x, out);
}